// round 3
// baseline (speedup 1.0000x reference)
#include <cuda_runtime.h>
#include <cstdint>

#define N_NODES 100000
#define NT 16     // NUM_TYPES
#define OD 128    // OUT_DIM

// Scratch (allocation-free rule: __device__ globals). 16B-aligned for float4.
__device__ __align__(16) float g_p[N_NODES * NT];
__device__ __align__(16) float g_msum[N_NODES * NT];
__device__ float g_deg[N_NODES];
__device__ int   g_idx64;   // 1 if indices are int64, 0 if int32

// ---------------------------------------------------------------------------
// Detect index width. int32 data misread as int64 gives values >= 2^32 with
// probability 1-1e-5 per element (hi half is a random node id, rarely 0).
// ---------------------------------------------------------------------------
__global__ void k_detect(const void* __restrict__ src, int E) {
    if (blockIdx.x == 0 && threadIdx.x == 0) {
        const unsigned long long* p = (const unsigned long long*)src;
        int is64 = 1;
        int lim = (E / 2 < 16) ? E / 2 : 16;
        for (int i = 0; i < lim; i++) {
            if (p[i] > 0x7FFFFFFFULL) is64 = 0;
        }
        g_idx64 = is64;
    }
}

// ---------------------------------------------------------------------------
// Zero msum / deg
// ---------------------------------------------------------------------------
__global__ void k_zero(int n) {
    int i = blockIdx.x * blockDim.x + threadIdx.x;
    int tot = n * NT;
    if (i < tot) g_msum[i] = 0.0f;
    if (i < n)   g_deg[i]  = 0.0f;
}

// ---------------------------------------------------------------------------
// p = softmax(relu(r@W1+b1) @ Wp + bp)   one thread per node
// W1: [16,128] row-major, Wp: [128,16] row-major
// ---------------------------------------------------------------------------
__global__ void k_compute_p(const float* __restrict__ r,
                            const float* __restrict__ W1,
                            const float* __restrict__ b1,
                            const float* __restrict__ Wp,
                            const float* __restrict__ bp,
                            int n) {
    __shared__ float sW1t[OD * NT];  // [j*16 + k] = W1[k*128 + j]
    __shared__ float sWp [OD * NT];  // [j*16 + t] = Wp[j*16 + t]
    __shared__ float sb1 [OD];
    __shared__ float sbp [NT];

    for (int i = threadIdx.x; i < OD * NT; i += blockDim.x) {
        int j = i >> 4, k = i & 15;
        sW1t[i] = W1[k * OD + j];
        sWp[i]  = Wp[i];
    }
    for (int i = threadIdx.x; i < OD; i += blockDim.x) sb1[i] = b1[i];
    if (threadIdx.x < NT) sbp[threadIdx.x] = bp[threadIdx.x];
    __syncthreads();

    int node = blockIdx.x * blockDim.x + threadIdx.x;
    if (node >= n) return;

    const float4* rp = (const float4*)(r + (size_t)node * NT);
    float4 r0 = rp[0], r1 = rp[1], r2 = rp[2], r3 = rp[3];

    float acc[NT];
#pragma unroll
    for (int t = 0; t < NT; t++) acc[t] = sbp[t];

    const float4* w1t4 = (const float4*)sW1t;
    const float4* wp4  = (const float4*)sWp;

#pragma unroll 4
    for (int j = 0; j < OD; j++) {
        float4 a = w1t4[j * 4 + 0];
        float4 b = w1t4[j * 4 + 1];
        float4 c = w1t4[j * 4 + 2];
        float4 d = w1t4[j * 4 + 3];
        float z = sb1[j];
        z = fmaf(r0.x, a.x, z); z = fmaf(r0.y, a.y, z);
        z = fmaf(r0.z, a.z, z); z = fmaf(r0.w, a.w, z);
        z = fmaf(r1.x, b.x, z); z = fmaf(r1.y, b.y, z);
        z = fmaf(r1.z, b.z, z); z = fmaf(r1.w, b.w, z);
        z = fmaf(r2.x, c.x, z); z = fmaf(r2.y, c.y, z);
        z = fmaf(r2.z, c.z, z); z = fmaf(r2.w, c.w, z);
        z = fmaf(r3.x, d.x, z); z = fmaf(r3.y, d.y, z);
        z = fmaf(r3.z, d.z, z); z = fmaf(r3.w, d.w, z);
        z = fmaxf(z, 0.0f);

        float4 p0 = wp4[j * 4 + 0];
        float4 p1 = wp4[j * 4 + 1];
        float4 p2 = wp4[j * 4 + 2];
        float4 p3 = wp4[j * 4 + 3];
        acc[0]  = fmaf(z, p0.x, acc[0]);  acc[1]  = fmaf(z, p0.y, acc[1]);
        acc[2]  = fmaf(z, p0.z, acc[2]);  acc[3]  = fmaf(z, p0.w, acc[3]);
        acc[4]  = fmaf(z, p1.x, acc[4]);  acc[5]  = fmaf(z, p1.y, acc[5]);
        acc[6]  = fmaf(z, p1.z, acc[6]);  acc[7]  = fmaf(z, p1.w, acc[7]);
        acc[8]  = fmaf(z, p2.x, acc[8]);  acc[9]  = fmaf(z, p2.y, acc[9]);
        acc[10] = fmaf(z, p2.z, acc[10]); acc[11] = fmaf(z, p2.w, acc[11]);
        acc[12] = fmaf(z, p3.x, acc[12]); acc[13] = fmaf(z, p3.y, acc[13]);
        acc[14] = fmaf(z, p3.z, acc[14]); acc[15] = fmaf(z, p3.w, acc[15]);
    }

    // softmax over 16 logits
    float m = acc[0];
#pragma unroll
    for (int t = 1; t < NT; t++) m = fmaxf(m, acc[t]);
    float s = 0.0f;
#pragma unroll
    for (int t = 0; t < NT; t++) { acc[t] = __expf(acc[t] - m); s += acc[t]; }
    float inv = 1.0f / s;

    float4* out4 = (float4*)(g_p + (size_t)node * NT);
    out4[0] = make_float4(acc[0] * inv, acc[1] * inv, acc[2] * inv, acc[3] * inv);
    out4[1] = make_float4(acc[4] * inv, acc[5] * inv, acc[6] * inv, acc[7] * inv);
    out4[2] = make_float4(acc[8] * inv, acc[9] * inv, acc[10] * inv, acc[11] * inv);
    out4[3] = make_float4(acc[12] * inv, acc[13] * inv, acc[14] * inv, acc[15] * inv);
}

// ---------------------------------------------------------------------------
// Scatter: msum[dst] += p[src], deg[dst] += 1
// 4 threads per edge; SCALAR f32 reductions only (v4 fp32 atomics trap on
// sm_100a with cudaErrorInvalidAddressSpace — sm_90a-only feature).
// ---------------------------------------------------------------------------
__global__ void k_scatter(const void* __restrict__ srcv,
                          const void* __restrict__ dstv,
                          int E, int n) {
    int gid = blockIdx.x * blockDim.x + threadIdx.x;
    int e = gid >> 2;
    if (e >= E) return;
    int q = gid & 3;

    int s, d;
    if (g_idx64) {
        s = (int)((const long long*)srcv)[e];
        d = (int)((const long long*)dstv)[e];
    } else {
        s = ((const int*)srcv)[e];
        d = ((const int*)dstv)[e];
    }
    // safety clamp: a bad index shows up as rel_err, not a crash
    s = min(max(s, 0), n - 1);
    d = min(max(d, 0), n - 1);

    const float4 v = *(const float4*)(g_p + (size_t)s * NT + q * 4);
    float* dp = g_msum + (size_t)d * NT + q * 4;
    atomicAdd(dp + 0, v.x);
    atomicAdd(dp + 1, v.y);
    atomicAdd(dp + 2, v.z);
    atomicAdd(dp + 3, v.w);
    if (q == 0) {
        atomicAdd(g_deg + d, 1.0f);
    }
}

// ---------------------------------------------------------------------------
// out = relu((msum/max(deg,1)) @ Wf + bf)   one thread per output element
// ---------------------------------------------------------------------------
__global__ void k_final(const float* __restrict__ Wf,
                        const float* __restrict__ bf,
                        float* __restrict__ out,
                        int n) {
    __shared__ float sWft[OD * NT];  // [j*16 + t] = Wf[t*128 + j]
    __shared__ float sbf [OD];
    for (int i = threadIdx.x; i < OD * NT; i += blockDim.x) {
        int j = i >> 4, t = i & 15;
        sWft[i] = Wf[t * OD + j];
    }
    for (int i = threadIdx.x; i < OD; i += blockDim.x) sbf[i] = bf[i];
    __syncthreads();

    int total  = n * OD;
    int stride = gridDim.x * blockDim.x;
    for (int gid = blockIdx.x * blockDim.x + threadIdx.x; gid < total; gid += stride) {
        int node = gid >> 7;
        int j    = gid & 127;

        float invd = 1.0f / fmaxf(g_deg[node], 1.0f);
        const float4* ms = (const float4*)(g_msum + (size_t)node * NT);
        float4 m0 = ms[0], m1 = ms[1], m2 = ms[2], m3 = ms[3];

        const float4* w = (const float4*)(sWft + j * NT);
        float4 a = w[0], b = w[1], c = w[2], d = w[3];

        float acc = 0.0f;
        acc = fmaf(m0.x, a.x, acc); acc = fmaf(m0.y, a.y, acc);
        acc = fmaf(m0.z, a.z, acc); acc = fmaf(m0.w, a.w, acc);
        acc = fmaf(m1.x, b.x, acc); acc = fmaf(m1.y, b.y, acc);
        acc = fmaf(m1.z, b.z, acc); acc = fmaf(m1.w, b.w, acc);
        acc = fmaf(m2.x, c.x, acc); acc = fmaf(m2.y, c.y, acc);
        acc = fmaf(m2.z, c.z, acc); acc = fmaf(m2.w, c.w, acc);
        acc = fmaf(m3.x, d.x, acc); acc = fmaf(m3.y, d.y, acc);
        acc = fmaf(m3.z, d.z, acc); acc = fmaf(m3.w, d.w, acc);

        acc = fmaf(invd, acc, sbf[j]);
        out[gid] = fmaxf(acc, 0.0f);
    }
}

// ---------------------------------------------------------------------------
// Inputs (metadata order): r, src, dst, W1, b1, Wp, bp, Wf, bf
// ---------------------------------------------------------------------------
extern "C" void kernel_launch(void* const* d_in, const int* in_sizes, int n_in,
                              void* d_out, int out_size) {
    const float* r   = (const float*)d_in[0];
    const void*  src = d_in[1];
    const void*  dst = d_in[2];
    const float* W1  = (const float*)d_in[3];
    const float* b1  = (const float*)d_in[4];
    const float* Wp  = (const float*)d_in[5];
    const float* bp  = (const float*)d_in[6];
    const float* Wf  = (const float*)d_in[7];
    const float* bf  = (const float*)d_in[8];
    float*       out = (float*)d_out;

    int n = in_sizes[0] / NT;   // N nodes
    int E = in_sizes[1];        // edges

    k_detect<<<1, 32>>>(src, E);

    {
        int tot = n * NT;
        k_zero<<<(tot + 255) / 256, 256>>>(n);
    }
    {
        k_compute_p<<<(n + 255) / 256, 256>>>(r, W1, b1, Wp, bp, n);
    }
    {
        long long threads = (long long)E * 4;
        int blocks = (int)((threads + 255) / 256);
        k_scatter<<<blocks, 256>>>(src, dst, E, n);
    }
    {
        k_final<<<3200, 256>>>(Wf, bf, out, n);
    }
}